// round 17
// baseline (speedup 1.0000x reference)
#include <cuda_runtime.h>
#include <cuda_fp16.h>
#include <cstdint>

typedef unsigned long long ull;

#define NN   30000
#define INC  128
#define OC   64
#define MP   4
#define EE   480000
#define FFD  2048
#define TOK  (NN*MP)
#define TOKP 120064                  // padded token count (multiple of 256)
#define FTB  128                     // tokens per ff block
#define NBF  (TOKP / FTB)            // 938
#define TBA  128                     // tokens per attn block
#define NBA  (TOKP / TBA)            // 938
#define JC   64                      // j per chunk (ff)
#define NCH  (FFD / JC)              // 32 chunks
#define CAP  128
#define LN_EPS 1e-5f

// ---- device scratch (zero-initialized at module load) ----
__device__ float g_y[(size_t)MP * NN * OC];
__device__ float g_c[(size_t)MP * NN * OC];
__device__ float g_e[(size_t)TOKP * OC];
__device__ int   g_cnt[MP * NN];
__device__ int   g_bkt[(size_t)MP * NN * CAP];

// ---- fp16 mma.sync helper ----
__device__ __forceinline__ void mma_f16(float* c, const unsigned* a, const unsigned* b) {
    asm volatile(
        "mma.sync.aligned.m16n8k16.row.col.f32.f16.f16.f32 "
        "{%0,%1,%2,%3}, {%4,%5,%6,%7}, {%8,%9}, {%0,%1,%2,%3};"
        : "+f"(c[0]), "+f"(c[1]), "+f"(c[2]), "+f"(c[3])
        : "r"(a[0]), "r"(a[1]), "r"(a[2]), "r"(a[3]), "r"(b[0]), "r"(b[1]));
}
__device__ __forceinline__ int hperm(int k) {
    return (k & ~15) | ((k & 6) << 1) | ((k & 8) >> 2) | (k & 1);
}
__device__ __forceinline__ unsigned pack_h2(float x, float y) {
    __half2 h = __floats2half2_rn(x, y);
    return *(unsigned*)&h;
}

// =====================================================================
// K_xw: y = x@Wl^T ; c = x@Wc^T + bias, fp16 mma.sync
// =====================================================================
__global__ void __launch_bounds__(512, 1) k_xw(
    const float* __restrict__ x,
    const float* __restrict__ W0, const float* __restrict__ b0,
    const float* __restrict__ Wl, const float* __restrict__ bl,
    const float* __restrict__ W1, const float* __restrict__ b1)
{
    extern __shared__ char smb[];
    __half* sX = (__half*)smb;               // [256][144]h
    __half* sW = (__half*)(smb + 73728);     // [128][144]h
    float*  sB = (float*)(smb + 110592);     // 64
    int t = threadIdx.x, w = t >> 5, lane = t & 31;
    int qr = lane >> 2, qc = lane & 3;
    int m = blockIdx.y;
    int node0 = blockIdx.x * 256;

    for (int i = t; i < 256 * 64; i += 512) {
        int row = i >> 6, kk = (i & 63) * 2;
        int gn = node0 + row; if (gn >= NN) gn = NN - 1;
        float2 f = *(const float2*)(x + (size_t)gn * INC + kk);
        *(__half2*)(sX + row * 144 + hperm(kk)) = __floats2half2_rn(f.x, f.y);
    }
    for (int i = t; i < 128 * 64; i += 512) {
        int r = i >> 6, kk = (i & 63) * 2;
        float2 f;
        if (r < 64) {
            f = *(const float2*)(Wl + (size_t)m * 8192 + (size_t)r * 128 + kk);
        } else {
            float2 a = *(const float2*)(W0 + (size_t)m * 8192 + (size_t)(r - 64) * 128 + kk);
            float2 b = *(const float2*)(W1 + (size_t)m * 8192 + (size_t)(r - 64) * 128 + kk);
            f = make_float2(a.x + b.x, a.y + b.y);
        }
        *(__half2*)(sW + r * 144 + hperm(kk)) = __floats2half2_rn(f.x, f.y);
    }
    if (t < 64) sB[t] = b0[m * 64 + t] + bl[m * 64 + t] + b1[m * 64 + t];
    __syncthreads();

    int mrow = (w & 7) * 32;
    int nh   = w >> 3;          // 0 -> y, 1 -> c

    float acc[2][8][4];
    #pragma unroll
    for (int nt = 0; nt < 8; nt++) {
        float bv0 = 0.f, bv1 = 0.f;
        if (nh == 1) { bv0 = sB[nt * 8 + 2 * qc]; bv1 = sB[nt * 8 + 2 * qc + 1]; }
        #pragma unroll
        for (int mt = 0; mt < 2; mt++) {
            acc[mt][nt][0] = bv0; acc[mt][nt][1] = bv1;
            acc[mt][nt][2] = bv0; acc[mt][nt][3] = bv1;
        }
    }
    #pragma unroll
    for (int k0 = 0; k0 < 128; k0 += 16) {
        unsigned a[2][4];
        #pragma unroll
        for (int mt = 0; mt < 2; mt++) {
            int r0 = mrow + mt * 16;
            ull vlo = *(const ull*)(sX + (r0 + qr) * 144 + k0 + 4 * qc);
            ull vhi = *(const ull*)(sX + (r0 + 8 + qr) * 144 + k0 + 4 * qc);
            a[mt][0] = (unsigned)vlo; a[mt][2] = (unsigned)(vlo >> 32);
            a[mt][1] = (unsigned)vhi; a[mt][3] = (unsigned)(vhi >> 32);
        }
        #pragma unroll
        for (int nt = 0; nt < 8; nt++) {
            ull bv = *(const ull*)(sW + (nh * 64 + nt * 8 + qr) * 144 + k0 + 4 * qc);
            unsigned b[2] = { (unsigned)bv, (unsigned)(bv >> 32) };
            mma_f16(acc[0][nt], a[0], b);
            mma_f16(acc[1][nt], a[1], b);
        }
    }
    float* dst = nh ? g_c : g_y;
    #pragma unroll
    for (int nt = 0; nt < 8; nt++) {
        int col = nt * 8 + 2 * qc;
        #pragma unroll
        for (int mt = 0; mt < 2; mt++) {
            int r0 = mrow + mt * 16 + qr;
            int n0 = node0 + r0, n1 = n0 + 8;
            if (n0 < NN)
                *(float2*)(dst + ((size_t)m * NN + n0) * OC + col) =
                    make_float2(acc[mt][nt][0], acc[mt][nt][1]);
            if (n1 < NN)
                *(float2*)(dst + ((size_t)m * NN + n1) * OC + col) =
                    make_float2(acc[mt][nt][2], acc[mt][nt][3]);
        }
    }
}

// =====================================================================
// K1: bucket edges by (m, src). g_cnt zeroed by k_gnn of the previous
// invocation (zero-initialized at module load for the first).
// =====================================================================
__global__ void k_bucket(const int* __restrict__ ei) {
    int eg = blockIdx.x * 256 + threadIdx.x;
    int m = eg / EE;
    int e = eg - m * EE;
    const int* b = ei + (size_t)m * 2 * EE;
    int src = __ldg(b + e);
    int dst = __ldg(b + EE + e);
    int gid = m * NN + src;
    int pos = atomicAdd(&g_cnt[gid], 1);
    if (pos < CAP) g_bkt[(size_t)gid * CAP + pos] = dst;
}

// =====================================================================
// K2: fused gather + GNN tail:
//   agg = sum_{bucket} y[dst]; h = relu(agg + c); e_m = (h@Wo^T + bo)*mpw
// 256 nodes/block, 512 threads; warp gathers 16 nodes then MMA.
// =====================================================================
__global__ void __launch_bounds__(512, 1) k_gnn(
    const float* __restrict__ Wo, const float* __restrict__ bo,
    const float* __restrict__ mpw)
{
    extern __shared__ char smb[];
    __half* sH  = (__half*)smb;              // [256][80]h
    __half* sWo = (__half*)(smb + 40960);    // [64][80]h
    float*  sBo = (float*)(smb + 51200);     // 64
    int t = threadIdx.x, w = t >> 5, lane = t & 31;
    int qr = lane >> 2, qc = lane & 3;
    int m = blockIdx.y;
    int node0 = blockIdx.x * 256;

    for (int i = t; i < 64 * 32; i += 512) {
        int r = i >> 5, kk = (i & 31) * 2;
        float2 f = *(const float2*)(Wo + (size_t)m * 4096 + (size_t)r * 64 + kk);
        *(__half2*)(sWo + r * 80 + hperm(kk)) = __floats2half2_rn(f.x, f.y);
    }
    if (t < 64) sBo[t] = bo[m * 64 + t];

    // gather phase: warp handles 16 nodes
    const float* yb = g_y + (size_t)m * NN * OC;
    int kk = 2 * lane;
    int kpos = hperm(kk);
    for (int ni = 0; ni < 16; ni++) {
        int lrow = w * 16 + ni;
        int gn = node0 + lrow;
        if (gn >= NN) {   // tail rows: zero (outputs discarded), don't touch cnt
            *(__half2*)(sH + lrow * 80 + kpos) = __floats2half2_rn(0.f, 0.f);
            continue;
        }
        int gid = m * NN + gn;
        int cnt = g_cnt[gid]; if (cnt > CAP) cnt = CAP;
        const int* bk = g_bkt + (size_t)gid * CAP;
        float ax = 0.f, ay = 0.f;
        for (int base = 0; base < cnt; base += 32) {
            int d = 0;
            if (base + lane < cnt) d = bk[base + lane];
            int lim = cnt - base; if (lim > 32) lim = 32;
            for (int j = 0; j < lim; j++) {
                int dd = __shfl_sync(0xffffffffu, d, j);
                float2 v = *(const float2*)(yb + (size_t)dd * OC + kk);
                ax += v.x; ay += v.y;
            }
        }
        float2 c = *(const float2*)(g_c + (size_t)gid * OC + kk);
        *(__half2*)(sH + lrow * 80 + kpos) =
            __floats2half2_rn(fmaxf(ax + c.x, 0.f), fmaxf(ay + c.y, 0.f));
        if (lane == 0) g_cnt[gid] = 0;
    }
    __syncthreads();

    int mrow = (w & 7) * 32;
    int nh   = w >> 3;
    float wgt = mpw[m];

    float acc[2][4][4];
    #pragma unroll
    for (int mt = 0; mt < 2; mt++)
        #pragma unroll
        for (int nt = 0; nt < 4; nt++)
            #pragma unroll
            for (int q = 0; q < 4; q++) acc[mt][nt][q] = 0.f;

    #pragma unroll
    for (int k0 = 0; k0 < 64; k0 += 16) {
        unsigned a[2][4];
        #pragma unroll
        for (int mt = 0; mt < 2; mt++) {
            int r0 = mrow + mt * 16;
            ull vlo = *(const ull*)(sH + (r0 + qr) * 80 + k0 + 4 * qc);
            ull vhi = *(const ull*)(sH + (r0 + 8 + qr) * 80 + k0 + 4 * qc);
            a[mt][0] = (unsigned)vlo; a[mt][2] = (unsigned)(vlo >> 32);
            a[mt][1] = (unsigned)vhi; a[mt][3] = (unsigned)(vhi >> 32);
        }
        #pragma unroll
        for (int nt = 0; nt < 4; nt++) {
            ull bv = *(const ull*)(sWo + (nh * 32 + nt * 8 + qr) * 80 + k0 + 4 * qc);
            unsigned b[2] = { (unsigned)bv, (unsigned)(bv >> 32) };
            mma_f16(acc[0][nt], a[0], b);
            mma_f16(acc[1][nt], a[1], b);
        }
    }
    #pragma unroll
    for (int nt = 0; nt < 4; nt++) {
        int col = nh * 32 + nt * 8 + 2 * qc;
        float bias0 = sBo[col], bias1 = sBo[col + 1];
        #pragma unroll
        for (int mt = 0; mt < 2; mt++) {
            int r0 = mrow + mt * 16 + qr;
            int n0 = node0 + r0, n1 = n0 + 8;
            if (n0 < NN)
                *(float2*)(g_e + ((size_t)n0 * MP + m) * OC + col) =
                    make_float2((acc[mt][nt][0] + bias0) * wgt, (acc[mt][nt][1] + bias1) * wgt);
            if (n1 < NN)
                *(float2*)(g_e + ((size_t)n1 * MP + m) * OC + col) =
                    make_float2((acc[mt][nt][2] + bias0) * wgt, (acc[mt][nt][3] + bias1) * wgt);
        }
    }
}

// =====================================================================
// K3: attention sublayer, 128-token tile (32 nodes), 256 threads, 2 CTA/SM.
// =====================================================================
__global__ void __launch_bounds__(256, 2) k_attn(
    const float* __restrict__ tinw, const float* __restrict__ tinb,
    const float* __restrict__ tow,  const float* __restrict__ tob,
    const float* __restrict__ g1,   const float* __restrict__ b1v, int l)
{
    extern __shared__ char smb[];
    __half* sE   = (__half*)smb;                 // [128][80]h (alias sAO)
    __half* sWin = (__half*)(smb + 20480);       // [192][80]h
    __half* sQKV = (__half*)(smb + 51200);       // [32 node][768]h (alias sO)
    __half* sWo  = (__half*)(smb + 100352);      // [64][80]h
    float*  sBin = (float*)(smb + 110592);       // 192
    float*  sBo  = (float*)(smb + 111360);       // 64
    __half* sAO  = sE;
    float*  sO   = (float*)(smb + 51200);        // epilogue [128][72]f
    int t = threadIdx.x, w = t >> 5, lane = t & 31;
    int qr = lane >> 2, qc = lane & 3;
    size_t tok0 = (size_t)blockIdx.x * TBA;

    const float* tw  = tinw + (size_t)l * 192 * 64;
    const float* twO = tow  + (size_t)l * 64 * 64;
    for (int i = t; i < 192 * 32; i += 256) {
        int r = i >> 5, kk = (i & 31) * 2;
        float2 f = *(const float2*)(tw + (size_t)r * 64 + kk);
        *(__half2*)(sWin + r * 80 + hperm(kk)) = __floats2half2_rn(f.x, f.y);
    }
    for (int i = t; i < 64 * 32; i += 256) {
        int r = i >> 5, kk = (i & 31) * 2;
        float2 f = *(const float2*)(twO + (size_t)r * 64 + kk);
        *(__half2*)(sWo + r * 80 + hperm(kk)) = __floats2half2_rn(f.x, f.y);
    }
    for (int i = t; i < TBA * 32; i += 256) {
        int row = i >> 5, kk = (i & 31) * 2;
        float2 f = *(const float2*)(g_e + (tok0 + row) * 64 + kk);
        *(__half2*)(sE + row * 80 + hperm(kk)) = __floats2half2_rn(f.x, f.y);
    }
    if (t < 192) sBin[t] = tinb[l * 192 + t];
    if (t >= 192 && t < 256) sBo[t - 192] = tob[l * 64 + (t - 192)];
    __syncthreads();

    int mrow = (w & 3) * 32;
    int nh   = w >> 2;

    #pragma unroll
    for (int np = 0; np < 2; np++) {
        float acc[2][6][4];
        #pragma unroll
        for (int nt = 0; nt < 6; nt++) {
            int col = nh * 96 + np * 48 + nt * 8 + 2 * qc;
            float bv0 = sBin[col], bv1 = sBin[col + 1];
            #pragma unroll
            for (int mt = 0; mt < 2; mt++) {
                acc[mt][nt][0] = bv0; acc[mt][nt][1] = bv1;
                acc[mt][nt][2] = bv0; acc[mt][nt][3] = bv1;
            }
        }
        #pragma unroll
        for (int k0 = 0; k0 < 64; k0 += 16) {
            unsigned a[2][4];
            #pragma unroll
            for (int mt = 0; mt < 2; mt++) {
                int r0 = mrow + mt * 16;
                ull vlo = *(const ull*)(sE + (r0 + qr) * 80 + k0 + 4 * qc);
                ull vhi = *(const ull*)(sE + (r0 + 8 + qr) * 80 + k0 + 4 * qc);
                a[mt][0] = (unsigned)vlo; a[mt][2] = (unsigned)(vlo >> 32);
                a[mt][1] = (unsigned)vhi; a[mt][3] = (unsigned)(vhi >> 32);
            }
            #pragma unroll
            for (int nt = 0; nt < 6; nt++) {
                ull bv = *(const ull*)(sWin + (nh * 96 + np * 48 + nt * 8 + qr) * 80 + k0 + 4 * qc);
                unsigned b[2] = { (unsigned)bv, (unsigned)(bv >> 32) };
                mma_f16(acc[0][nt], a[0], b);
                mma_f16(acc[1][nt], a[1], b);
            }
        }
        #pragma unroll
        for (int nt = 0; nt < 6; nt++) {
            int col = nh * 96 + np * 48 + nt * 8 + 2 * qc;
            #pragma unroll
            for (int mt = 0; mt < 2; mt++) {
                int r0 = mrow + mt * 16 + qr;
                int r1 = r0 + 8;
                *(__half2*)(sQKV + (r0 >> 2) * 768 + (r0 & 3) * 192 + col) =
                    __floats2half2_rn(acc[mt][nt][0], acc[mt][nt][1]);
                *(__half2*)(sQKV + (r1 >> 2) * 768 + (r1 & 3) * 192 + col) =
                    __floats2half2_rn(acc[mt][nt][2], acc[mt][nt][3]);
            }
        }
    }
    __syncthreads();

    #pragma unroll
    for (int it = 0; it < 4; it++) {
        int u = it * 256 + t;
        int node = u >> 5, hd = (u >> 2) & 7, mq = u & 3;
        const __half* base = sQKV + node * 768;
        float q[8];
        #pragma unroll
        for (int d = 0; d < 4; d++) {
            float2 f = __half22float2(*(const __half2*)(base + mq * 192 + hd * 8 + 2 * d));
            q[2 * d] = f.x; q[2 * d + 1] = f.y;
        }
        float sc[4];
        #pragma unroll
        for (int mk = 0; mk < 4; mk++) {
            const __half* kp = base + mk * 192 + 64 + hd * 8;
            float a = 0.f;
            #pragma unroll
            for (int d = 0; d < 4; d++) {
                float2 f = __half22float2(*(const __half2*)(kp + 2 * d));
                a = fmaf(q[2 * d], f.x, a); a = fmaf(q[2 * d + 1], f.y, a);
            }
            sc[mk] = a * 0.35355339059327373f;
        }
        float mx = fmaxf(fmaxf(sc[0], sc[1]), fmaxf(sc[2], sc[3]));
        float p[4]; float psum = 0.f;
        #pragma unroll
        for (int mk = 0; mk < 4; mk++) { p[mk] = __expf(sc[mk] - mx); psum += p[mk]; }
        float inv = 1.0f / psum;
        float o[8];
        #pragma unroll
        for (int d = 0; d < 8; d++) o[d] = 0.f;
        #pragma unroll
        for (int mk = 0; mk < 4; mk++) {
            const __half* vp = base + mk * 192 + 128 + hd * 8;
            float pw = p[mk] * inv;
            #pragma unroll
            for (int d = 0; d < 4; d++) {
                float2 f = __half22float2(*(const __half2*)(vp + 2 * d));
                o[2 * d]     = fmaf(pw, f.x, o[2 * d]);
                o[2 * d + 1] = fmaf(pw, f.y, o[2 * d + 1]);
            }
        }
        int row = node * 4 + mq;
        #pragma unroll
        for (int d = 0; d < 4; d++) {
            int col = hd * 8 + 2 * d;
            *(__half2*)(sAO + row * 80 + hperm(col)) = __floats2half2_rn(o[2 * d], o[2 * d + 1]);
        }
    }
    __syncthreads();

    {
        float acc[2][4][4];
        #pragma unroll
        for (int mt = 0; mt < 2; mt++)
            #pragma unroll
            for (int nt = 0; nt < 4; nt++)
                #pragma unroll
                for (int q = 0; q < 4; q++) acc[mt][nt][q] = 0.f;
        #pragma unroll
        for (int k0 = 0; k0 < 64; k0 += 16) {
            unsigned a[2][4];
            #pragma unroll
            for (int mt = 0; mt < 2; mt++) {
                int r0 = mrow + mt * 16;
                ull vlo = *(const ull*)(sAO + (r0 + qr) * 80 + k0 + 4 * qc);
                ull vhi = *(const ull*)(sAO + (r0 + 8 + qr) * 80 + k0 + 4 * qc);
                a[mt][0] = (unsigned)vlo; a[mt][2] = (unsigned)(vlo >> 32);
                a[mt][1] = (unsigned)vhi; a[mt][3] = (unsigned)(vhi >> 32);
            }
            #pragma unroll
            for (int nt = 0; nt < 4; nt++) {
                ull bv = *(const ull*)(sWo + (nh * 32 + nt * 8 + qr) * 80 + k0 + 4 * qc);
                unsigned b[2] = { (unsigned)bv, (unsigned)(bv >> 32) };
                mma_f16(acc[0][nt], a[0], b);
                mma_f16(acc[1][nt], a[1], b);
            }
        }
        __syncthreads();
        #pragma unroll
        for (int nt = 0; nt < 4; nt++) {
            int col = nh * 32 + nt * 8 + 2 * qc;
            float bias0 = sBo[col], bias1 = sBo[col + 1];
            #pragma unroll
            for (int mt = 0; mt < 2; mt++) {
                int r0 = mrow + mt * 16 + qr;
                int r1 = r0 + 8;
                float2 e0 = *(const float2*)(g_e + (tok0 + r0) * 64 + col);
                float2 e1 = *(const float2*)(g_e + (tok0 + r1) * 64 + col);
                sO[r0 * 72 + col]     = acc[mt][nt][0] + bias0 + e0.x;
                sO[r0 * 72 + col + 1] = acc[mt][nt][1] + bias1 + e0.y;
                sO[r1 * 72 + col]     = acc[mt][nt][2] + bias0 + e1.x;
                sO[r1 * 72 + col + 1] = acc[mt][nt][3] + bias1 + e1.y;
            }
        }
    }
    __syncthreads();

    int tk2 = t >> 1, half = t & 1;
    const float* ob = sO + tk2 * 72 + half * 32;
    float s = 0.f, s2 = 0.f;
    #pragma unroll
    for (int i = 0; i < 32; i++) { float v = ob[i]; s += v; s2 += v * v; }
    s  += __shfl_xor_sync(0xffffffffu, s, 1);
    s2 += __shfl_xor_sync(0xffffffffu, s2, 1);
    float mu   = s * (1.f / 64.f);
    float rstd = rsqrtf(s2 * (1.f / 64.f) - mu * mu + LN_EPS);
    float* go = g_e + (tok0 + tk2) * 64 + half * 32;
    #pragma unroll
    for (int i = 0; i < 32; i++) {
        int c = half * 32 + i;
        go[i] = (ob[i] - mu) * rstd * g1[l * 64 + c] + b1v[l * 64 + c];
    }
}

// =====================================================================
// K4: FF on fp16 mma.sync, 128-token tile, 256 threads, 2 CTA/SM.
// Register-resident H (C-frag == A-frag), double-buffered weights.
// =====================================================================
__global__ void __launch_bounds__(256, 2) k_ff(
    const float* __restrict__ ff1w, const float* __restrict__ ff1b,
    const float* __restrict__ ff2w, const float* __restrict__ ff2b,
    const float* __restrict__ g2,   const float* __restrict__ b2, int l)
{
    extern __shared__ char smb[];
    __half* sE  = (__half*)smb;              // [128][80]h = 20480B
    __half* sW1 = (__half*)(smb + 20480);    // [2][64][80]h = 20480B
    __half* sW2 = (__half*)(smb + 40960);    // [2][64][80]h = 20480B
    float*  sB1 = (float*)(smb + 61440);     // [2][64]
    float*  sO  = (float*)smb;               // alias epilogue [128][72]f = 36864B
    int t = threadIdx.x, w = t >> 5, lane = t & 31;
    int qr = lane >> 2, qc = lane & 3;
    size_t tok0 = (size_t)blockIdx.x * FTB;
    int mrow = w * 16;

    const float* f1w = ff1w + (size_t)l * FFD * OC;
    const float* f1b = ff1b + (size_t)l * FFD;
    const float* f2w = ff2w + (size_t)l * OC * FFD;

    for (int i = t; i < FTB * 32; i += 256) {
        int row = i >> 5, kk = (i & 31) * 2;
        float2 f = *(const float2*)(g_e + tok0 * 64 + (size_t)row * 64 + kk);
        *(__half2*)(sE + row * 80 + hperm(kk)) = __floats2half2_rn(f.x, f.y);
    }
    for (int i = t; i < JC * 32; i += 256) {
        int j = i >> 5, kk = (i & 31) * 2;
        float2 f = *(const float2*)(f1w + (size_t)j * 64 + kk);
        *(__half2*)(sW1 + j * 80 + hperm(kk)) = __floats2half2_rn(f.x, f.y);
    }
    for (int i = t; i < 64 * 32; i += 256) {
        int c = i >> 5, jj = (i & 31) * 2;
        float2 f = *(const float2*)(f2w + (size_t)c * FFD + jj);
        *(__half2*)(sW2 + c * 80 + hperm(jj)) = __floats2half2_rn(f.x, f.y);
    }
    if (t < 64) sB1[t] = f1b[t];
    __syncthreads();

    float acc2[8][4];
    #pragma unroll
    for (int nt = 0; nt < 8; nt++)
        #pragma unroll
        for (int q = 0; q < 4; q++) acc2[nt][q] = 0.f;

    for (int ch = 0; ch < NCH; ch++) {
        int buf = ch & 1, nb = buf ^ 1;
        const __half* w1 = sW1 + buf * 5120;
        const __half* w2 = sW2 + buf * 5120;
        const float*  bb = sB1 + buf * 64;
        int jb2 = (ch + 1) * JC;

        // prefetch next chunk's weights (packed to half2 immediately: 16 regs)
        unsigned w1n[8], w2n[8]; float b1n = 0.f;
        if (ch < NCH - 1) {
            #pragma unroll
            for (int r = 0; r < 8; r++) {
                int idx = t + r * 256;
                int j = idx >> 5, kk = (idx & 31) * 2;
                float2 f = *(const float2*)(f1w + (size_t)(jb2 + j) * 64 + kk);
                w1n[r] = pack_h2(f.x, f.y);
            }
            #pragma unroll
            for (int r = 0; r < 8; r++) {
                int idx = t + r * 256;
                int c = idx >> 5, jj = (idx & 31) * 2;
                float2 f = *(const float2*)(f2w + (size_t)c * FFD + jb2 + jj);
                w2n[r] = pack_h2(f.x, f.y);
            }
            if (t < 64) b1n = f1b[jb2 + t];
        }

        float acc1[8][4];
        #pragma unroll
        for (int nt = 0; nt < 8; nt++) {
            float bv0 = bb[nt * 8 + 2 * qc];
            float bv1 = bb[nt * 8 + 2 * qc + 1];
            acc1[nt][0] = bv0; acc1[nt][1] = bv1;
            acc1[nt][2] = bv0; acc1[nt][3] = bv1;
        }
        #pragma unroll
        for (int k0 = 0; k0 < 64; k0 += 16) {
            ull vlo = *(const ull*)(sE + (mrow + qr) * 80 + k0 + 4 * qc);
            ull vhi = *(const ull*)(sE + (mrow + 8 + qr) * 80 + k0 + 4 * qc);
            unsigned a[4] = { (unsigned)vlo, (unsigned)vhi,
                              (unsigned)(vlo >> 32), (unsigned)(vhi >> 32) };
            #pragma unroll
            for (int nt = 0; nt < 8; nt++) {
                ull bv = *(const ull*)(w1 + (nt * 8 + qr) * 80 + k0 + 4 * qc);
                unsigned b[2] = { (unsigned)bv, (unsigned)(bv >> 32) };
                mma_f16(acc1[nt], a, b);
            }
        }

        unsigned afr[4][4];
        #pragma unroll
        for (int kt = 0; kt < 4; kt++) {
            afr[kt][0] = pack_h2(fmaxf(acc1[2 * kt][0], 0.f),     fmaxf(acc1[2 * kt][1], 0.f));
            afr[kt][1] = pack_h2(fmaxf(acc1[2 * kt][2], 0.f),     fmaxf(acc1[2 * kt][3], 0.f));
            afr[kt][2] = pack_h2(fmaxf(acc1[2 * kt + 1][0], 0.f), fmaxf(acc1[2 * kt + 1][1], 0.f));
            afr[kt][3] = pack_h2(fmaxf(acc1[2 * kt + 1][2], 0.f), fmaxf(acc1[2 * kt + 1][3], 0.f));
        }

        #pragma unroll
        for (int kt = 0; kt < 4; kt++) {
            #pragma unroll
            for (int nt = 0; nt < 8; nt++) {
                ull bv = *(const ull*)(w2 + (nt * 8 + qr) * 80 + kt * 16 + 4 * qc);
                unsigned b[2] = { (unsigned)bv, (unsigned)(bv >> 32) };
                mma_f16(acc2[nt], afr[kt], b);
            }
        }

        if (ch < NCH - 1) {
            #pragma unroll
            for (int r = 0; r < 8; r++) {
                int idx = t + r * 256;
                int j = idx >> 5, kk = (idx & 31) * 2;
                *(unsigned*)(sW1 + nb * 5120 + j * 80 + hperm(kk)) = w1n[r];
            }
            #pragma unroll
            for (int r = 0; r < 8; r++) {
                int idx = t + r * 256;
                int c = idx >> 5, jj = (idx & 31) * 2;
                *(unsigned*)(sW2 + nb * 5120 + c * 80 + hperm(jj)) = w2n[r];
            }
            if (t < 64) sB1[nb * 64 + t] = b1n;
        }
        __syncthreads();
    }

    #pragma unroll
    for (int nt = 0; nt < 8; nt++) {
        int col = nt * 8 + 2 * qc;
        float bias0 = ff2b[l * OC + col];
        float bias1 = ff2b[l * OC + col + 1];
        int r0 = mrow + qr, r1 = r0 + 8;
        float2 e0 = *(const float2*)(g_e + (tok0 + r0) * 64 + col);
        float2 e1 = *(const float2*)(g_e + (tok0 + r1) * 64 + col);
        sO[r0 * 72 + col]     = acc2[nt][0] + bias0 + e0.x;
        sO[r0 * 72 + col + 1] = acc2[nt][1] + bias1 + e0.y;
        sO[r1 * 72 + col]     = acc2[nt][2] + bias0 + e1.x;
        sO[r1 * 72 + col + 1] = acc2[nt][3] + bias1 + e1.y;
    }
    __syncthreads();

    int tk2 = t >> 1, half = t & 1;
    const float* ob = sO + tk2 * 72 + half * 32;
    float s = 0.f, s2 = 0.f;
    #pragma unroll
    for (int i = 0; i < 32; i++) { float v = ob[i]; s += v; s2 += v * v; }
    s  += __shfl_xor_sync(0xffffffffu, s, 1);
    s2 += __shfl_xor_sync(0xffffffffu, s2, 1);
    float mu   = s * (1.f / 64.f);
    float rstd = rsqrtf(s2 * (1.f / 64.f) - mu * mu + LN_EPS);
    float* go = g_e + (tok0 + tk2) * 64 + half * 32;
    #pragma unroll
    for (int i = 0; i < 32; i++) {
        int c = half * 32 + i;
        go[i] = (ob[i] - mu) * rstd * g2[l * OC + c] + b2[l * OC + c];
    }
}

// =====================================================================
// K5: head
// =====================================================================
__global__ void __launch_bounds__(256) k_head(
    const float* __restrict__ r1w, const float* __restrict__ r1b,
    const float* __restrict__ r2w, const float* __restrict__ r2b,
    float* __restrict__ out)
{
    __shared__ float sR1T[64 * 65];
    __shared__ float sR2[64];
    __shared__ float sP[8][64];
    int t = threadIdx.x;
    for (int i = t; i < 4096; i += 256) {
        int c = i >> 6, k = i & 63;
        sR1T[k * 65 + c] = r1w[c * 64 + k];
    }
    if (t < 64) sR2[t] = r2w[t];
    __syncthreads();
    int w = t >> 5, lane = t & 31;
    int n = blockIdx.x * 8 + w;
    const float* eb = g_e + (size_t)n * 256;
    float p0 = (eb[lane] + eb[64 + lane] + eb[128 + lane] + eb[192 + lane]) * 0.25f;
    float p1 = (eb[32 + lane] + eb[96 + lane] + eb[160 + lane] + eb[224 + lane]) * 0.25f;
    sP[w][lane]      = p0;
    sP[w][lane + 32] = p1;
    __syncwarp();
    float a0 = r1b[lane], a1 = r1b[lane + 32];
    #pragma unroll 8
    for (int k = 0; k < 64; k++) {
        float pv = sP[w][k];
        a0 = fmaf(pv, sR1T[k * 65 + lane], a0);
        a1 = fmaf(pv, sR1T[k * 65 + lane + 32], a1);
    }
    a0 = fmaxf(a0, 0.f); a1 = fmaxf(a1, 0.f);
    float acc = a0 * sR2[lane] + a1 * sR2[lane + 32];
    #pragma unroll
    for (int off = 16; off; off >>= 1) acc += __shfl_xor_sync(0xffffffffu, acc, off);
    if (lane == 0) out[n] = acc + r2b[0];
}

// =====================================================================
extern "C" void kernel_launch(void* const* d_in, const int* in_sizes, int n_in,
                              void* d_out, int out_size) {
    const float* x    = (const float*)d_in[0];
    const int*   ei   = (const int*)  d_in[1];
    const float* mpw  = (const float*)d_in[2];
    const float* W0   = (const float*)d_in[3];
    const float* b0   = (const float*)d_in[4];
    const float* Wl   = (const float*)d_in[5];
    const float* bl   = (const float*)d_in[6];
    const float* W1   = (const float*)d_in[7];
    const float* b1   = (const float*)d_in[8];
    const float* Wo   = (const float*)d_in[9];
    const float* bo   = (const float*)d_in[10];
    const float* tinw = (const float*)d_in[11];
    const float* tinb = (const float*)d_in[12];
    const float* tow  = (const float*)d_in[13];
    const float* tob  = (const float*)d_in[14];
    const float* ln1g = (const float*)d_in[15];
    const float* ln1b = (const float*)d_in[16];
    const float* ff1w = (const float*)d_in[17];
    const float* ff1b = (const float*)d_in[18];
    const float* ff2w = (const float*)d_in[19];
    const float* ff2b = (const float*)d_in[20];
    const float* ln2g = (const float*)d_in[21];
    const float* ln2b = (const float*)d_in[22];
    const float* r1w  = (const float*)d_in[23];
    const float* r1b  = (const float*)d_in[24];
    const float* r2w  = (const float*)d_in[25];
    const float* r2b  = (const float*)d_in[26];
    float* out = (float*)d_out;
    (void)in_sizes; (void)n_in; (void)out_size;

    cudaFuncSetAttribute(k_xw,   cudaFuncAttributeMaxDynamicSharedMemorySize, 110848);
    cudaFuncSetAttribute(k_gnn,  cudaFuncAttributeMaxDynamicSharedMemorySize, 51456);
    cudaFuncSetAttribute(k_attn, cudaFuncAttributeMaxDynamicSharedMemorySize, 111616);
    cudaFuncSetAttribute(k_ff,   cudaFuncAttributeMaxDynamicSharedMemorySize, 61952);

    dim3 gxw(118, 4);
    k_bucket<<<7500, 256>>>(ei);                                             // 1
    k_xw<<<gxw, 512, 110848>>>(x, W0, b0, Wl, bl, W1, b1);                   // 2
    k_gnn<<<gxw, 512, 51456>>>(Wo, bo, mpw);                                 // 3
    k_attn<<<NBA, 256, 111616>>>(tinw, tinb, tow, tob, ln1g, ln1b, 0);       // 4
    k_ff<<<NBF, 256, 61952>>>(ff1w, ff1b, ff2w, ff2b, ln2g, ln2b, 0);        // 5
    k_attn<<<NBA, 256, 111616>>>(tinw, tinb, tow, tob, ln1g, ln1b, 1);       // 6 <- ncu
    k_ff<<<NBF, 256, 61952>>>(ff1w, ff1b, ff2w, ff2b, ln2g, ln2b, 1);        // 7
    k_head<<<3750, 256>>>(r1w, r1b, r2w, r2b, out);                          // 8
}